// round 13
// baseline (speedup 1.0000x reference)
#include <cuda_runtime.h>
#include <cuda_bf16.h>
#include <cstdint>

#define B_BATCH   128
#define T_STEPS   500
#define K_DIM     700
#define KP        704
#define N_DIM     1024
#define M_DIM     64000

#define PHI_C    0.36787944117144233f
#define GAMMA_C  0.8187307530779818f
#define BETA_C   0.9048374180359595f
#define U_TH_C   1.0f
#define EPS_FLAG 2.0e-4f

__device__ float g_inputs[(size_t)M_DIM * N_DIM];
__device__ __nv_bfloat16 g_asplit[3ull * M_DIM * KP];
__device__ __nv_bfloat16 g_bsplit[3ull * N_DIM * KP];
__device__ unsigned char g_flags[B_BATCH * N_DIM];

#define A_PLANE ((size_t)M_DIM * KP)
#define B_PLANE ((size_t)N_DIM * KP)

// ---------------------------------------------------------------------------
// Split: fp32 -> 3x bf16 planes (hi, mid, lo), K zero-padded to 704
// ---------------------------------------------------------------------------
__global__ __launch_bounds__(256) void split_kernel(
    const float* __restrict__ src, __nv_bfloat16* __restrict__ dst,
    int rows, size_t plane)
{
    int idx = blockIdx.x * blockDim.x + threadIdx.x;
    int r = idx / (KP / 8);
    int u = idx % (KP / 8);
    if (r >= rows) return;
    int k = u * 8;
    __nv_bfloat16 h0[8], h1[8], h2[8];
#pragma unroll
    for (int i = 0; i < 8; i++) {
        float x = (k + i < K_DIM) ? src[(size_t)r * K_DIM + k + i] : 0.0f;
        __nv_bfloat16 a = __float2bfloat16(x);
        float r1 = x - __bfloat162float(a);
        __nv_bfloat16 b = __float2bfloat16(r1);
        float r2 = r1 - __bfloat162float(b);
        h0[i] = a; h1[i] = b; h2[i] = __float2bfloat16(r2);
    }
    size_t off = (size_t)r * KP + k;
    *(uint4*)(dst + off)             = *(uint4*)h0;
    *(uint4*)(dst + plane + off)     = *(uint4*)h1;
    *(uint4*)(dst + 2 * plane + off) = *(uint4*)h2;
}

// ---------------------------------------------------------------------------
// Hybrid GEMM, 512 threads. CTA = 128x128 tile, C[m,n] = sum_k A[m,k]W[n,k].
//  warps 0-7  (2/SMSP): cols [0,96)   bit-exact fp32 FFMA
//  warps 8-15 (2/SMSP): cols [96,128) bf16 3-split 6-product mma.sync
// ---------------------------------------------------------------------------
#define T_APL     10240                    // A plane: 128 rows x 80 B
#define T_BPL     2560                     // B plane: 32 rows x 80 B
#define T_STAGE   (3 * T_APL + 3 * T_BPL)  // 38400
#define T_NST     3
#define T_NCH     22                       // 704/32
#define FP_OFF    (T_NST * T_STAGE)        // 115200 B
#define AS_STRIDE 132
#define BS_STRIDE 100
#define AS_OFF_F  (FP_OFF / 4)
#define BS_OFF_F  (FP_OFF / 4 + 16 * AS_STRIDE)
#define DYN_SMEM  (FP_OFF + (16 * AS_STRIDE + 16 * BS_STRIDE) * 4)  // 130048
#define F_NCH     44                       // 704/16

__device__ __forceinline__ uint32_t smem_u32(const void* p) {
    uint32_t a;
    asm("{ .reg .u64 t; cvta.to.shared.u64 t, %1; cvt.u32.u64 %0, t; }" : "=r"(a) : "l"(p));
    return a;
}
__device__ __forceinline__ void ldsm_x4(uint32_t addr, uint32_t& r0, uint32_t& r1,
                                        uint32_t& r2, uint32_t& r3) {
    asm volatile("ldmatrix.sync.aligned.m8n8.x4.shared.b16 {%0,%1,%2,%3}, [%4];"
                 : "=r"(r0), "=r"(r1), "=r"(r2), "=r"(r3) : "r"(addr));
}
__device__ __forceinline__ void mma16816(float* d, const uint32_t* a, const uint32_t* b) {
    asm volatile(
        "mma.sync.aligned.m16n8k16.row.col.f32.bf16.bf16.f32 "
        "{%0,%1,%2,%3}, {%4,%5,%6,%7}, {%8,%9}, {%0,%1,%2,%3};"
        : "+f"(d[0]), "+f"(d[1]), "+f"(d[2]), "+f"(d[3])
        : "r"(a[0]), "r"(a[1]), "r"(a[2]), "r"(a[3]), "r"(b[0]), "r"(b[1]));
}
__device__ __forceinline__ void bar_named(int id, int cnt) {
    asm volatile("bar.sync %0, %1;" :: "r"(id), "r"(cnt) : "memory");
}

// tensor stage loader: 256 threads, one 32-k chunk (3 A planes + 3 B planes)
__device__ __forceinline__ void t_load_stage(
    int chunk, int s, int ltid, int m0, int n0, uint32_t smem_base,
    const __nv_bfloat16* __restrict__ Asp, const __nv_bfloat16* __restrict__ Bsp)
{
    const int k0 = chunk * 32;
    const uint32_t sb = smem_base + s * T_STAGE;
#pragma unroll
    for (int it = 0; it < 8; ++it) {
        int idx = ltid + it * 256;            // 0..2047, need 1920
        if (idx >= 1920) break;
        const __nv_bfloat16* src;
        uint32_t dst;
        if (idx < 1536) {                     // A: 3 planes x 512 chunks
            int tile = idx >> 9, rem = idx & 511, r = rem >> 2, u = rem & 3;
            src = Asp + (size_t)tile * A_PLANE + (size_t)(m0 + r) * KP + k0 + u * 8;
            dst = sb + tile * T_APL + r * 80 + u * 16;
        } else {                              // B: 3 planes x 128 chunks
            int ib = idx - 1536;
            int tile = ib >> 7, rem = ib & 127, r = rem >> 2, u = rem & 3;
            src = Bsp + (size_t)tile * B_PLANE + (size_t)(n0 + 96 + r) * KP + k0 + u * 8;
            dst = sb + 3 * T_APL + tile * T_BPL + r * 80 + u * 16;
        }
        asm volatile("cp.async.cg.shared.global [%0], [%1], 16;" :: "r"(dst), "l"(src));
    }
    asm volatile("cp.async.commit_group;" ::: "memory");
}

__global__ __launch_bounds__(512, 1) void gemm_hybrid_kernel(
    const float* __restrict__ X,
    const float* __restrict__ W,
    const __nv_bfloat16* __restrict__ Asp,
    const __nv_bfloat16* __restrict__ Bsp,
    float* __restrict__ C)
{
    extern __shared__ __align__(128) char smem[];
    const uint32_t smem_base = smem_u32(smem);
    float* smf = (float*)smem;
    const int tid  = threadIdx.x;
    const int lane = tid & 31;
    const int wid  = tid >> 5;
    const int m0   = blockIdx.y * 128;
    const int n0   = blockIdx.x * 128;

    if (wid < 8) {
        // ============ fp32 group: 256 threads, cols [0,96) =================
        const int ltid = tid;                 // 0..255
        const int trow = ltid >> 4;           // 0..15
        const int tcol = ltid & 15;           // 0..15
        const int mloc = trow * 8;
        // thread covers cols {2*tcol + 32*j + d}, j<3, d<2

        float acc[8][6];
#pragma unroll
        for (int i = 0; i < 8; i++)
#pragma unroll
            for (int j = 0; j < 6; j++) acc[i][j] = 0.f;

        float4 av[2], bv[2];
        // prefetch chunk 0
        {
#pragma unroll
            for (int l = 0; l < 2; ++l) {
                int f = ltid + l * 256, row = f >> 2, u = f & 3, kg = u * 4;
                av[l] = (kg < K_DIM) ? *(const float4*)(X + (size_t)(m0 + row) * K_DIM + kg)
                                     : make_float4(0, 0, 0, 0);
            }
            bv[0] = make_float4(0, 0, 0, 0);
            bv[1] = make_float4(0, 0, 0, 0);
            {
                int f = ltid, row = f >> 2, u = f & 3, kg = u * 4;
                if (kg < K_DIM)
                    bv[0] = *(const float4*)(W + (size_t)(n0 + row) * K_DIM + kg);
            }
            if (ltid < 128) {
                int f = ltid + 256, row = f >> 2, u = f & 3, kg = u * 4;
                if (kg < K_DIM)
                    bv[1] = *(const float4*)(W + (size_t)(n0 + row) * K_DIM + kg);
            }
        }

        for (int c = 0; c < F_NCH; ++c) {
            // store prefetched regs -> smem transposed
#pragma unroll
            for (int l = 0; l < 2; ++l) {
                int f = ltid + l * 256, row = f >> 2, u = f & 3;
                smf[AS_OFF_F + (u * 4 + 0) * AS_STRIDE + row] = av[l].x;
                smf[AS_OFF_F + (u * 4 + 1) * AS_STRIDE + row] = av[l].y;
                smf[AS_OFF_F + (u * 4 + 2) * AS_STRIDE + row] = av[l].z;
                smf[AS_OFF_F + (u * 4 + 3) * AS_STRIDE + row] = av[l].w;
            }
            {
                int f = ltid, row = f >> 2, u = f & 3;
                smf[BS_OFF_F + (u * 4 + 0) * BS_STRIDE + row] = bv[0].x;
                smf[BS_OFF_F + (u * 4 + 1) * BS_STRIDE + row] = bv[0].y;
                smf[BS_OFF_F + (u * 4 + 2) * BS_STRIDE + row] = bv[0].z;
                smf[BS_OFF_F + (u * 4 + 3) * BS_STRIDE + row] = bv[0].w;
            }
            if (ltid < 128) {
                int f = ltid + 256, row = f >> 2, u = f & 3;
                smf[BS_OFF_F + (u * 4 + 0) * BS_STRIDE + row] = bv[1].x;
                smf[BS_OFF_F + (u * 4 + 1) * BS_STRIDE + row] = bv[1].y;
                smf[BS_OFF_F + (u * 4 + 2) * BS_STRIDE + row] = bv[1].z;
                smf[BS_OFF_F + (u * 4 + 3) * BS_STRIDE + row] = bv[1].w;
            }
            bar_named(1, 256);

            // prefetch next chunk
            if (c + 1 < F_NCH) {
                const int k0 = (c + 1) * 16;
#pragma unroll
                for (int l = 0; l < 2; ++l) {
                    int f = ltid + l * 256, row = f >> 2, u = f & 3, kg = k0 + u * 4;
                    av[l] = (kg < K_DIM) ? *(const float4*)(X + (size_t)(m0 + row) * K_DIM + kg)
                                         : make_float4(0, 0, 0, 0);
                }
                {
                    int f = ltid, row = f >> 2, u = f & 3, kg = k0 + u * 4;
                    bv[0] = (kg < K_DIM) ? *(const float4*)(W + (size_t)(n0 + row) * K_DIM + kg)
                                         : make_float4(0, 0, 0, 0);
                }
                if (ltid < 128) {
                    int f = ltid + 256, row = f >> 2, u = f & 3, kg = k0 + u * 4;
                    bv[1] = (kg < K_DIM) ? *(const float4*)(W + (size_t)(n0 + row) * K_DIM + kg)
                                         : make_float4(0, 0, 0, 0);
                }
            }

            // 16 ascending k-steps (bit-exact chain per (m,n))
#pragma unroll
            for (int k = 0; k < 16; ++k) {
                float4 a0 = *(float4*)&smf[AS_OFF_F + k * AS_STRIDE + mloc];
                float4 a1 = *(float4*)&smf[AS_OFF_F + k * AS_STRIDE + mloc + 4];
                float2 b0 = *(float2*)&smf[BS_OFF_F + k * BS_STRIDE + 2 * tcol];
                float2 b1 = *(float2*)&smf[BS_OFF_F + k * BS_STRIDE + 2 * tcol + 32];
                float2 b2 = *(float2*)&smf[BS_OFF_F + k * BS_STRIDE + 2 * tcol + 64];
                float a[8] = {a0.x, a0.y, a0.z, a0.w, a1.x, a1.y, a1.z, a1.w};
                float b[6] = {b0.x, b0.y, b1.x, b1.y, b2.x, b2.y};
#pragma unroll
                for (int i = 0; i < 8; ++i)
#pragma unroll
                    for (int j = 0; j < 6; ++j)
                        acc[i][j] = fmaf(a[i], b[j], acc[i][j]);
            }
            bar_named(1, 256);
        }

        // epilogue: float2 per (i, j)
#pragma unroll
        for (int i = 0; i < 8; ++i) {
            float* cp = C + (size_t)(m0 + mloc + i) * N_DIM + n0 + 2 * tcol;
#pragma unroll
            for (int j = 0; j < 3; ++j)
                *(float2*)(cp + 32 * j) = make_float2(acc[i][2 * j], acc[i][2 * j + 1]);
        }
    } else {
        // ============ tensor group: 256 threads, cols [96,128) =============
        const int ltid = tid - 256;           // 0..255
        const int twid = ltid >> 5;           // 0..7
        const int rw   = twid >> 1;           // 0..3: rows rw*32
        const int cw   = twid & 1;            // 0..1: cols cw*16

        float acc[2][2][4];
#pragma unroll
        for (int i = 0; i < 2; i++)
#pragma unroll
            for (int j = 0; j < 2; j++)
#pragma unroll
                for (int f = 0; f < 4; f++) acc[i][j][f] = 0.f;

        t_load_stage(0, 0, ltid, m0, n0, smem_base, Asp, Bsp);
        t_load_stage(1, 1, ltid, m0, n0, smem_base, Asp, Bsp);

        const uint32_t a_row = lane & 15;
        const uint32_t a_kb  = ((lane >> 4) & 1) * 16;
        const uint32_t b_row = ((lane >> 4) & 1) * 8 + (lane & 7);
        const uint32_t b_kb  = ((lane >> 3) & 1) * 16;

        for (int c = 0; c < T_NCH; ++c) {
            const int s = c % T_NST;
            if (c == T_NCH - 1)
                asm volatile("cp.async.wait_group 0;" ::: "memory");
            else
                asm volatile("cp.async.wait_group 1;" ::: "memory");
            bar_named(2, 256);

            if (c + 2 < T_NCH)
                t_load_stage(c + 2, (c + 2) % T_NST, ltid, m0, n0, smem_base, Asp, Bsp);

            const uint32_t sA = smem_base + s * T_STAGE;
            const uint32_t sB = sA + 3 * T_APL;
#pragma unroll
            for (int ks = 0; ks < 2; ++ks) {
                uint32_t bf[3][2][2];
#pragma unroll
                for (int q = 0; q < 3; ++q) {
                    uint32_t addr = sB + q * T_BPL + (cw * 16 + b_row) * 80
                                  + ks * 32 + b_kb;
                    ldsm_x4(addr, bf[q][0][0], bf[q][0][1], bf[q][1][0], bf[q][1][1]);
                }
#pragma unroll
                for (int p = 0; p < 3; ++p) {
                    uint32_t af[2][4];
#pragma unroll
                    for (int im = 0; im < 2; ++im) {
                        uint32_t addr = sA + p * T_APL
                                      + (rw * 32 + im * 16 + a_row) * 80 + ks * 32 + a_kb;
                        ldsm_x4(addr, af[im][0], af[im][1], af[im][2], af[im][3]);
                    }
#pragma unroll
                    for (int q = 0; q < 3; ++q) {
                        if (p + q > 2) continue;
#pragma unroll
                        for (int im = 0; im < 2; ++im)
#pragma unroll
                            for (int jn = 0; jn < 2; ++jn)
                                mma16816(acc[im][jn], af[im], bf[q][jn]);
                    }
                }
            }
            bar_named(2, 256);
        }

        const int erow = lane >> 2;
        const int ecol = (lane & 3) * 2;
#pragma unroll
        for (int im = 0; im < 2; ++im)
#pragma unroll
            for (int jn = 0; jn < 2; ++jn) {
                float* cp = C + (size_t)(m0 + rw * 32 + im * 16 + erow) * N_DIM
                              + n0 + 96 + cw * 16 + jn * 8 + ecol;
                *(float2*)cp = make_float2(acc[im][jn][0], acc[im][jn][1]);
                *(float2*)(cp + 8 * N_DIM) = make_float2(acc[im][jn][2], acc[im][jn][3]);
            }
    }
}

// ---------------------------------------------------------------------------
// LIF scan + flag: 4 channels per thread (float4 I/O)
// ---------------------------------------------------------------------------
__global__ __launch_bounds__(256) void lif_scan_flag_kernel(
    const float* __restrict__ inp, float* __restrict__ Uo,
    float* __restrict__ So, unsigned char* __restrict__ flags)
{
    int idx = blockIdx.x * blockDim.x + threadIdx.x;   // 0..32767
    int b  = idx >> 8;
    int h0 = (idx & 255) * 4;
    size_t base = (size_t)b * T_STEPS * N_DIM + h0;

    const float* ip = inp + base;
    float* up = Uo + base;
    float* sp = So + base;

    *(float4*)up = make_float4(0, 0, 0, 0);
    *(float4*)sp = make_float4(0, 0, 0, 0);

    float H[4] = {0, 0, 0, 0}, I[4] = {0, 0, 0, 0};
    float U[4] = {0, 0, 0, 0}, S[4] = {0, 0, 0, 0};
    int flagged[4] = {0, 0, 0, 0};
#pragma unroll 2
    for (int t = 1; t < T_STEPS; t++) {
        float4 xv = *(const float4*)(ip + (size_t)(t - 1) * N_DIM);
        float x[4] = {xv.x, xv.y, xv.z, xv.w};
        float4 uv, sv;
        float* uo = (float*)&uv;
        float* so = (float*)&sv;
#pragma unroll
        for (int e = 0; e < 4; ++e) {
            float Hn = PHI_C * H[e] + x[e];
            float In = GAMMA_C * I[e] + H[e];
            float Un = BETA_C * (U[e] - I[e]) - S[e];
            float Sn = (Un > U_TH_C) ? 1.0f : 0.0f;
            flagged[e] |= (fabsf(Un - U_TH_C) < EPS_FLAG) ? 1 : 0;
            uo[e] = Un; so[e] = Sn;
            H[e] = Hn; I[e] = In; U[e] = Un; S[e] = Sn;
        }
        *(float4*)(up + (size_t)t * N_DIM) = uv;
        *(float4*)(sp + (size_t)t * N_DIM) = sv;
    }
    uchar4 fv;
    fv.x = (unsigned char)(flagged[0] && (((h0 + 0) & 127) >= 96));
    fv.y = (unsigned char)(flagged[1] && (((h0 + 1) & 127) >= 96));
    fv.z = (unsigned char)(flagged[2] && (((h0 + 2) & 127) >= 96));
    fv.w = (unsigned char)(flagged[3] && (((h0 + 3) & 127) >= 96));
    *(uchar4*)(flags + b * N_DIM + h0) = fv;
}

// ---------------------------------------------------------------------------
// Repair: bit-exact recompute of flagged channels (one block per batch)
// ---------------------------------------------------------------------------
#define NH_BATCH 8
#define RPR_SX    0
#define RPR_SW    16500
#define RPR_SINP  (16500 + 5632)
#define RPR_SMEM  ((16500 + 5632 + 4000) * 4)

__global__ __launch_bounds__(512) void lif_repair_kernel(
    const float* __restrict__ X, const float* __restrict__ W,
    const unsigned char* __restrict__ flags,
    float* __restrict__ Uo, float* __restrict__ So)
{
    extern __shared__ float rsm[];
    float* sX   = rsm + RPR_SX;
    float* sW   = rsm + RPR_SW;
    float* sInp = rsm + RPR_SINP;
    __shared__ int hlist[N_DIM];
    __shared__ int hcount;

    const int b = blockIdx.x;
    const int tid = threadIdx.x;

    if (tid == 0) {
        int cnt = 0;
        for (int h = 0; h < N_DIM; ++h)
            if (flags[b * N_DIM + h]) hlist[cnt++] = h;
        hcount = cnt;
    }
    __syncthreads();
    const int nflag = hcount;

    for (int bi = 0; bi < nflag; bi += NH_BATCH) {
        const int nh = min(NH_BATCH, nflag - bi);
        for (int i = tid; i < nh * 704; i += 512) {
            int j = i / 704, k = i - j * 704;
            sW[j * 704 + k] = (k < K_DIM) ? W[(size_t)hlist[bi + j] * K_DIM + k] : 0.f;
        }
        __syncthreads();

        float c8[NH_BATCH];
#pragma unroll
        for (int j = 0; j < NH_BATCH; ++j) c8[j] = 0.f;

        for (int kc = 0; kc < K_DIM; kc += 32) {
            const int kw = (K_DIM - kc < 32) ? (K_DIM - kc) : 32;
            for (int i = tid; i < T_STEPS * kw; i += 512) {
                int tt = i / kw, kk = i - tt * kw;
                sX[tt * 33 + kk] = X[((size_t)b * T_STEPS + tt) * K_DIM + kc + kk];
            }
            __syncthreads();
            if (tid < T_STEPS) {
#pragma unroll
                for (int j = 0; j < NH_BATCH; ++j) {
                    float c = c8[j];
                    for (int kk = 0; kk < kw; ++kk)
                        c = fmaf(sX[tid * 33 + kk], sW[j * 704 + kc + kk], c);
                    c8[j] = c;
                }
            }
            __syncthreads();
        }
        if (tid < T_STEPS)
#pragma unroll
            for (int j = 0; j < NH_BATCH; ++j)
                if (j < nh) sInp[j * T_STEPS + tid] = c8[j];
        __syncthreads();

        if (tid < nh) {
            const int h = hlist[bi + tid];
            size_t base = (size_t)b * T_STEPS * N_DIM + h;
            Uo[base] = 0.0f;
            So[base] = 0.0f;
            float H = 0.f, I = 0.f, U = 0.f, S = 0.f;
            for (int t = 1; t < T_STEPS; t++) {
                float x  = sInp[tid * T_STEPS + (t - 1)];
                float Hn = PHI_C * H + x;
                float In = GAMMA_C * I + H;
                float Un = BETA_C * (U - I) - S;
                float Sn = (Un > U_TH_C) ? 1.0f : 0.0f;
                Uo[base + (size_t)t * N_DIM] = Un;
                So[base + (size_t)t * N_DIM] = Sn;
                H = Hn; I = In; U = Un; S = Sn;
            }
        }
        __syncthreads();
    }
}

// ---------------------------------------------------------------------------
extern "C" void kernel_launch(void* const* d_in, const int* in_sizes, int n_in,
                              void* d_out, int out_size)
{
    const float* X = (const float*)d_in[0];
    const float* W = (const float*)d_in[1];
    float* out = (float*)d_out;

    float* inputs;           cudaGetSymbolAddress((void**)&inputs, g_inputs);
    __nv_bfloat16* asplit;   cudaGetSymbolAddress((void**)&asplit, g_asplit);
    __nv_bfloat16* bsplit;   cudaGetSymbolAddress((void**)&bsplit, g_bsplit);
    unsigned char* flags;    cudaGetSymbolAddress((void**)&flags, g_flags);

    cudaFuncSetAttribute(gemm_hybrid_kernel,
                         cudaFuncAttributeMaxDynamicSharedMemorySize, DYN_SMEM);
    cudaFuncSetAttribute(lif_repair_kernel,
                         cudaFuncAttributeMaxDynamicSharedMemorySize, RPR_SMEM);

    split_kernel<<<(M_DIM * (KP / 8) + 255) / 256, 256>>>(X, asplit, M_DIM, A_PLANE);
    split_kernel<<<(N_DIM * (KP / 8) + 255) / 256, 256>>>(W, bsplit, N_DIM, B_PLANE);

    dim3 ggrid(N_DIM / 128, M_DIM / 128);     // (8, 500)
    gemm_hybrid_kernel<<<ggrid, 512, DYN_SMEM>>>(X, W, asplit, bsplit, inputs);

    float* Uo = out;
    float* So = out + (size_t)B_BATCH * T_STEPS * N_DIM;
    lif_scan_flag_kernel<<<B_BATCH, 256>>>(inputs, Uo, So, flags);
    lif_repair_kernel<<<B_BATCH, 512, RPR_SMEM>>>(X, W, flags, Uo, So);
}